// round 10
// baseline (speedup 1.0000x reference)
#include <cuda_runtime.h>
#include <cstdint>

// ---------------- problem constants ----------------
#define B_    2
#define S_    2048
#define D_    1024
#define H_    16
#define DK_   64
#define BH_   (B_*H_)        // 32
#define M_    (B_*S_)        // 4096
#define LNEPS 1e-6f
#define INVTEMP 0.125f       // 1/sqrt(64)

// ---------------- device scratch (static; no allocations) ----------------
__device__ float g_q[(size_t)BH_*S_*DK_];     // tf32-pre-rounded
__device__ float g_k[(size_t)BH_*S_*DK_];     // tf32-pre-rounded
__device__ float g_v[(size_t)BH_*S_*DK_];     // tf32-pre-rounded
__device__ float g_o[(size_t)M_*D_];
__device__ float g_fc[(size_t)M_*D_];
__device__ float g_rsum[BH_*S_];
__device__ float g_attn[(size_t)BH_*S_*S_];   // fallback if attn not in d_out

// ---------------- tf32 / cp.async helpers ----------------
__device__ __forceinline__ uint32_t tf32r(float f){
    uint32_t u; asm("cvt.rna.tf32.f32 %0,%1;" : "=r"(u) : "f"(f)); return u;
}
__device__ __forceinline__ void cpa16(uint32_t s, const void* g){
    asm volatile("cp.async.cg.shared.global [%0],[%1],16;" :: "r"(s), "l"(g));
}
#define CPA_COMMIT() asm volatile("cp.async.commit_group;")
#define CPA_WAIT(N)  asm volatile("cp.async.wait_group %0;" :: "n"(N))

#define MMA_TF32(c,a,b) \
  asm volatile("mma.sync.aligned.m16n8k8.row.col.f32.tf32.tf32.f32 " \
    "{%0,%1,%2,%3},{%4,%5,%6,%7},{%8,%9},{%0,%1,%2,%3};" \
    : "+f"(c[0]),"+f"(c[1]),"+f"(c[2]),"+f"(c[3]) \
    : "r"(a[0]),"r"(a[1]),"r"(a[2]),"r"(a[3]),"r"(b[0]),"r"(b[1]))

// 32-deep K-chunk, B in k-major [k][BP].
template<int NB, int AP, int BP>
__device__ __forceinline__ void mma_chunk(const uint32_t* As, const uint32_t* Bs,
        int wm, int wn, int lane, float (*c)[NB][4])
{
    const int r = lane >> 2, q = lane & 3;
    #pragma unroll
    for (int ks = 0; ks < 4; ks++) {
        const int k0 = ks * 8;
        uint32_t a[2][4], b[NB][2];
        #pragma unroll
        for (int im = 0; im < 2; im++) {
            const uint32_t* ap = As + (size_t)(wm + 16*im + r) * AP + k0 + q;
            a[im][0] = ap[0];      a[im][1] = ap[8*AP];
            a[im][2] = ap[4];      a[im][3] = ap[8*AP + 4];
        }
        #pragma unroll
        for (int jn = 0; jn < NB; jn++) {
            const uint32_t* bp = Bs + (size_t)(k0 + q) * BP + wn + 8*jn + r;
            b[jn][0] = bp[0];      b[jn][1] = bp[4*BP];
        }
        #pragma unroll
        for (int im = 0; im < 2; im++)
            #pragma unroll
            for (int jn = 0; jn < NB; jn++)
                MMA_TF32(c[im][jn], a[im], b[jn]);
    }
}

// 32-deep K-chunk, B in n-major [n][BP] (keys as rows; no transpose staging).
template<int NB, int AP, int BP>
__device__ __forceinline__ void mma_chunk_bn(const uint32_t* As, const uint32_t* Bn,
        int koff, int wm, int wn, int lane, float (*c)[NB][4])
{
    const int r = lane >> 2, q = lane & 3;
    #pragma unroll
    for (int ks = 0; ks < 4; ks++) {
        const int k0 = koff + ks * 8;
        uint32_t a[2][4], b[NB][2];
        #pragma unroll
        for (int im = 0; im < 2; im++) {
            const uint32_t* ap = As + (size_t)(wm + 16*im + r) * AP + k0 + q;
            a[im][0] = ap[0];      a[im][1] = ap[8*AP];
            a[im][2] = ap[4];      a[im][3] = ap[8*AP + 4];
        }
        #pragma unroll
        for (int jn = 0; jn < NB; jn++) {
            const uint32_t* bp = Bn + (size_t)(wn + 8*jn + r) * BP + k0 + q;
            b[jn][0] = bp[0];      b[jn][1] = bp[4];
        }
        #pragma unroll
        for (int im = 0; im < 2; im++)
            #pragma unroll
            for (int jn = 0; jn < NB; jn++)
                MMA_TF32(c[im][jn], a[im], b[jn]);
    }
}

// ---------------- block reduction (blockDim == 256) ----------------
__device__ __forceinline__ float bred_sum(float v, float* red){
    #pragma unroll
    for (int o = 16; o; o >>= 1) v += __shfl_xor_sync(0xffffffffu, v, o);
    if ((threadIdx.x & 31) == 0) red[threadIdx.x >> 5] = v;
    __syncthreads();
    float r = red[0];
    #pragma unroll
    for (int i = 1; i < 8; i++) r += red[i];
    __syncthreads();
    return r;
}

// =======================================================================
// K1: QKV projections (tf32 MMA). Writes Q/K/V PRE-ROUNDED to tf32.
// =======================================================================
__global__ __launch_bounds__(256)
void k_proj(const float* __restrict__ X,
            const float* __restrict__ Wq,
            const float* __restrict__ Wk,
            const float* __restrict__ Wv)
{
    __shared__ uint32_t As[128*36];
    __shared__ uint32_t Bs[32*136];
    const int z = blockIdx.z;
    const float* W = (z == 0) ? Wq : (z == 1) ? Wk : Wv;
    float* DST     = (z == 0) ? g_q : (z == 1) ? g_k : g_v;
    const int n0 = blockIdx.x * 128, m0 = blockIdx.y * 128;
    const int t = threadIdx.x, lane = t & 31, wid = t >> 5;
    const int wm = (wid & 3) * 32, wn = (wid >> 2) * 64;

    float c[2][8][4];
    #pragma unroll
    for (int i=0;i<2;i++)
        #pragma unroll
        for (int j=0;j<8;j++)
            #pragma unroll
            for (int k=0;k<4;k++) c[i][j][k]=0.f;

    for (int k0 = 0; k0 < 1024; k0 += 32) {
        #pragma unroll
        for (int p = 0; p < 4; p++) {               // A: 128x32
            int f = t + p*256, r = f >> 3, c4 = f & 7;
            float4 v = *(const float4*)&X[(size_t)(m0+r)*1024 + k0 + c4*4];
            uint32_t* d = &As[r*36 + c4*4];
            d[0]=tf32r(v.x); d[1]=tf32r(v.y); d[2]=tf32r(v.z); d[3]=tf32r(v.w);
        }
        #pragma unroll
        for (int p = 0; p < 4; p++) {               // B: 32x128
            int f = t + p*256, r = f >> 5, c4 = f & 31;
            float4 v = *(const float4*)&W[(size_t)(k0+r)*1024 + n0 + c4*4];
            uint32_t* d = &Bs[r*136 + c4*4];
            d[0]=tf32r(v.x); d[1]=tf32r(v.y); d[2]=tf32r(v.z); d[3]=tf32r(v.w);
        }
        __syncthreads();
        mma_chunk<8,36,136>(As, Bs, wm, wn, lane, c);
        __syncthreads();
    }
    const int r = lane >> 2, q4 = lane & 3;
    #pragma unroll
    for (int im = 0; im < 2; im++) {
        #pragma unroll
        for (int jn = 0; jn < 8; jn++) {
            const int n = n0 + wn + 8*jn + 2*q4;
            const int hh = n >> 6, nc = n & 63;
            #pragma unroll
            for (int hr = 0; hr < 2; hr++) {
                const int m = m0 + wm + 16*im + r + 8*hr;
                const int b = m >> 11, s = m & 2047;
                // pre-round to tf32 so k_attn can cp.async raw
                *(float2*)&DST[(((size_t)(b*H_ + hh))*S_ + s)*DK_ + nc] =
                    make_float2(__uint_as_float(tf32r(c[im][jn][2*hr])),
                                __uint_as_float(tf32r(c[im][jn][2*hr+1])));
            }
        }
    }
}

// =======================================================================
// K2: k_attn — single-pass attention with cp.async pipelined K/V:
//   wait K -> QK mma -> prefetch K(t+1) -> exp/store/stage (cover)
//   -> wait V -> PV mma -> prefetch V(t+1)
// Q/K/V are pre-rounded tf32: raw copies, zero in-loop conversion.
// K consumed n-major [key][68]; V k-major [key][72].
// =======================================================================
__global__ __launch_bounds__(256, 2)
void k_attn(const int* __restrict__ mask, float* __restrict__ attn_ext)
{
    extern __shared__ uint32_t sh[];
    uint32_t* Qs = sh;                     // [128][68]  8704 w
    uint32_t* Ps = sh + 8704;              // [128][68]  8704 w
    uint32_t* Ks = sh + 17408;             // [64][68]   4352 w (n-major)
    uint32_t* Vs = sh + 21760;             // [64][72]   4608 w (k-major)
    float* s_red = (float*)(sh + 26368);   // [2][128]
    float* s_inv = s_red + 256;            // [128]

    float* attn = attn_ext ? attn_ext : g_attn;
    const int bh = blockIdx.y, b = bh >> 4, h = bh & 15;
    const int m0 = blockIdx.x * 128;
    const float* Q = g_q + (size_t)bh * S_ * DK_ + (size_t)m0 * DK_;
    const float* K = g_k + (size_t)bh * S_ * DK_;
    const float* V = g_v + (size_t)bh * S_ * DK_;
    const int t = threadIdx.x, lane = t & 31, wid = t >> 5;
    const int wm = (wid & 3) * 32, wc = wid >> 2, wn = wc * 32;
    const int r8 = lane >> 2, q4 = lane & 3;

    const uint32_t qb = (uint32_t)__cvta_generic_to_shared(Qs);
    const uint32_t kb = (uint32_t)__cvta_generic_to_shared(Ks);
    const uint32_t vb = (uint32_t)__cvta_generic_to_shared(Vs);

    // prologue: async-copy Q tile, K0, V0 (three commit groups)
    #pragma unroll
    for (int p = 0; p < 8; p++) {          // Q: 128 rows x 256B
        int f = t + p*256, row = f >> 4, c16 = f & 15;
        cpa16(qb + (row*68 + c16*4)*4, Q + row*64 + c16*4);
    }
    CPA_COMMIT();
    #pragma unroll
    for (int p = 0; p < 4; p++) {          // K0: 64 rows x 256B
        int f = t + p*256, row = f >> 4, c16 = f & 15;
        cpa16(kb + (row*68 + c16*4)*4, K + row*64 + c16*4);
    }
    CPA_COMMIT();
    #pragma unroll
    for (int p = 0; p < 4; p++) {          // V0
        int f = t + p*256, row = f >> 4, c16 = f & 15;
        cpa16(vb + (row*72 + c16*4)*4, V + row*64 + c16*4);
    }
    CPA_COMMIT();

    float acc[2][4][4];
    #pragma unroll
    for (int i=0;i<2;i++)
        #pragma unroll
        for (int j=0;j<4;j++)
            #pragma unroll
            for (int k=0;k<4;k++) acc[i][j][k]=0.f;
    float s_acc[4] = {0.f, 0.f, 0.f, 0.f};

    for (int kt = 0; kt < 32; kt++) {
        // 1) K(kt) (and Q) resident; V(kt) may still be in flight
        CPA_WAIT(1);
        __syncthreads();

        // 2) QK^T: Q[128x64] x K^T -> c[128x64]
        float c[2][4][4];
        #pragma unroll
        for (int i=0;i<2;i++)
            #pragma unroll
            for (int j=0;j<4;j++)
                #pragma unroll
                for (int k=0;k<4;k++) c[i][j][k]=0.f;
        mma_chunk_bn<4,68,68>(Qs, Ks, 0,  wm, wn, lane, c);
        mma_chunk_bn<4,68,68>(Qs, Ks, 32, wm, wn, lane, c);
        __syncthreads();                   // all warps done reading Ks

        // 3) prefetch K(kt+1) into Ks (latency covered by exp phase)
        if (kt < 31) {
            const float* Kn = K + (size_t)(kt+1)*64*64;
            #pragma unroll
            for (int p = 0; p < 4; p++) {
                int f = t + p*256, row = f >> 4, c16 = f & 15;
                cpa16(kb + (row*68 + c16*4)*4, Kn + row*64 + c16*4);
            }
            CPA_COMMIT();
        }

        // 4) e = mask ? exp(l) : 0 ; write unnormalized e + stage + row sums
        const int n0 = kt * 64;
        #pragma unroll
        for (int im = 0; im < 2; im++)
        #pragma unroll
        for (int hr = 0; hr < 2; hr++) {
            const int rowloc = wm + 16*im + 8*hr + r8;
            const int qg = m0 + rowloc;
            const size_t mrow = (size_t)b*S_*S_ + (size_t)qg*S_;
            const size_t arow = ((size_t)bh*S_ + qg) * S_;
            float s = 0.f;
            #pragma unroll
            for (int jn = 0; jn < 4; jn++) {
                const int colloc = wn + 8*jn + 2*q4;
                const int col = n0 + colloc;
                const int2 mk = *(const int2*)&mask[mrow + col];
                const float ex = mk.x ? __expf(c[im][jn][2*hr]   * INVTEMP) : 0.f;
                const float ey = mk.y ? __expf(c[im][jn][2*hr+1] * INVTEMP) : 0.f;
                s += ex + ey;
                *(float2*)&attn[arow + col] = make_float2(ex, ey);
                Ps[rowloc*68 + colloc]     = tf32r(ex);
                Ps[rowloc*68 + colloc + 1] = tf32r(ey);
            }
            s_acc[im*2 + hr] += s;
        }

        // 5) V(kt) resident (K(kt+1) may still be in flight)
        if (kt < 31) { CPA_WAIT(1); } else { CPA_WAIT(0); }
        __syncthreads();                   // Ps ready + Vs visible

        // 6) PV: acc += P[128x64] x V[64x64]
        mma_chunk<4,68,72>(Ps,      Vs,         wm, wn, lane, acc);
        mma_chunk<4,68,72>(Ps + 32, Vs + 32*72, wm, wn, lane, acc);
        __syncthreads();                   // all warps done reading Vs

        // 7) prefetch V(kt+1) (latency covered by next QK + exp)
        if (kt < 31) {
            const float* Vn = V + (size_t)(kt+1)*64*64;
            #pragma unroll
            for (int p = 0; p < 4; p++) {
                int f = t + p*256, row = f >> 4, c16 = f & 15;
                cpa16(vb + (row*72 + c16*4)*4, Vn + row*64 + c16*4);
            }
            CPA_COMMIT();
        }
    }

    // row-sum reduction: q4 lanes -> warp-column partials -> total
    #pragma unroll
    for (int im = 0; im < 2; im++)
    #pragma unroll
    for (int hr = 0; hr < 2; hr++) {
        const int rowloc = wm + 16*im + 8*hr + r8;
        float s = s_acc[im*2 + hr];
        s += __shfl_xor_sync(0xffffffffu, s, 1);
        s += __shfl_xor_sync(0xffffffffu, s, 2);
        if (q4 == 0) s_red[wc*128 + rowloc] = s;
    }
    __syncthreads();
    if (t < 128) {
        const float tot = s_red[t] + s_red[128 + t];
        g_rsum[bh*S_ + m0 + t] = tot;
        s_inv[t] = 1.f / tot;
    }
    __syncthreads();

    // epilogue: O = acc * inv, merged [b*S+q][h*64+n]
    #pragma unroll
    for (int im = 0; im < 2; im++)
    #pragma unroll
    for (int hr = 0; hr < 2; hr++) {
        const int rowloc = wm + 16*im + 8*hr + r8;
        const int qg = m0 + rowloc;
        const float inv = s_inv[rowloc];
        float* orow = &g_o[(size_t)(b*S_ + qg)*D_ + h*DK_];
        #pragma unroll
        for (int jn = 0; jn < 4; jn++) {
            const int n = wn + 8*jn + 2*q4;
            *(float2*)&orow[n] = make_float2(acc[im][jn][2*hr] * inv,
                                             acc[im][jn][2*hr+1] * inv);
        }
    }
}

// =======================================================================
// K3: k_scale — attn[row][*] *= 1/rowsum. Dedicated streaming kernel
// (measured faster than folding into k_attn's tail: R7 vs R9).
// =======================================================================
__global__ __launch_bounds__(256)
void k_scale(float* __restrict__ attn_ext)
{
    float* attn = attn_ext ? attn_ext : g_attn;
    const int row = blockIdx.x;            // 0 .. BH_*S_-1
    const float inv = 1.f / g_rsum[row];
    float4* p = (float4*)(attn + (size_t)row * S_);
    const int t = threadIdx.x;
    #pragma unroll
    for (int u = 0; u < 2; u++) {
        float4 v = p[t + 256*u];
        v.x *= inv; v.y *= inv; v.z *= inv; v.w *= inv;
        p[t + 256*u] = v;
    }
}

// =======================================================================
// K4: fc = O[4096,1024] @ w_fc[1024,1024] + residual (tf32)
// =======================================================================
__global__ __launch_bounds__(256)
void k_fc(const float* __restrict__ X, const float* __restrict__ W)
{
    __shared__ uint32_t As[128*36];
    __shared__ uint32_t Bs[32*136];
    const int n0 = blockIdx.x * 128, m0 = blockIdx.y * 128;
    const int t = threadIdx.x, lane = t & 31, wid = t >> 5;
    const int wm = (wid & 3) * 32, wn = (wid >> 2) * 64;

    float c[2][8][4];
    #pragma unroll
    for (int i=0;i<2;i++)
        #pragma unroll
        for (int j=0;j<8;j++)
            #pragma unroll
            for (int k=0;k<4;k++) c[i][j][k]=0.f;

    for (int k0 = 0; k0 < 1024; k0 += 32) {
        #pragma unroll
        for (int p = 0; p < 4; p++) {
            int f = t + p*256, r = f >> 3, c4 = f & 7;
            float4 v = *(const float4*)&g_o[(size_t)(m0+r)*1024 + k0 + c4*4];
            uint32_t* d = &As[r*36 + c4*4];
            d[0]=tf32r(v.x); d[1]=tf32r(v.y); d[2]=tf32r(v.z); d[3]=tf32r(v.w);
        }
        #pragma unroll
        for (int p = 0; p < 4; p++) {
            int f = t + p*256, r = f >> 5, c4 = f & 31;
            float4 v = *(const float4*)&W[(size_t)(k0+r)*1024 + n0 + c4*4];
            uint32_t* d = &Bs[r*136 + c4*4];
            d[0]=tf32r(v.x); d[1]=tf32r(v.y); d[2]=tf32r(v.z); d[3]=tf32r(v.w);
        }
        __syncthreads();
        mma_chunk<8,36,136>(As, Bs, wm, wn, lane, c);
        __syncthreads();
    }
    const int r = lane >> 2, q4 = lane & 3;
    #pragma unroll
    for (int im = 0; im < 2; im++) {
        #pragma unroll
        for (int hr = 0; hr < 2; hr++) {
            const int m = m0 + wm + 16*im + r + 8*hr;
            #pragma unroll
            for (int jn = 0; jn < 8; jn++) {
                const int n = n0 + wn + 8*jn + 2*q4;
                const float2 res = *(const float2*)&X[(size_t)m*D_ + n];
                *(float2*)&g_fc[(size_t)m*D_ + n] =
                    make_float2(c[im][jn][2*hr] + res.x, c[im][jn][2*hr+1] + res.y);
            }
        }
    }
}

// =======================================================================
// K5: LayerNorm over last dim (1024), write final out region.
// =======================================================================
__global__ __launch_bounds__(256)
void k_ln(const float* __restrict__ gamma, const float* __restrict__ beta,
          float* __restrict__ out)
{
    __shared__ float red[8];
    const int m = blockIdx.x, t = threadIdx.x;
    const float* x = g_fc + (size_t)m * D_;
    float v[4];
    #pragma unroll
    for (int u = 0; u < 4; u++) v[u] = x[t + 256 * u];
    float s = v[0] + v[1] + v[2] + v[3];
    const float mu = bred_sum(s, red) * (1.0f / D_);
    float d2 = 0.f;
    #pragma unroll
    for (int u = 0; u < 4; u++) { float d = v[u] - mu; d2 += d * d; }
    const float var = bred_sum(d2, red) * (1.0f / D_);
    const float rstd = rsqrtf(var + LNEPS);
    #pragma unroll
    for (int u = 0; u < 4; u++) {
        const int c = t + 256 * u;
        out[(size_t)m * D_ + c] = (v[u] - mu) * rstd * gamma[c] + beta[c];
    }
}

// =======================================================================
extern "C" void kernel_launch(void* const* d_in, const int* in_sizes, int n_in,
                              void* d_out, int out_size)
{
    (void)in_sizes; (void)n_in;
    const float* qkv  = (const float*)d_in[0];
    const int*   mask = (const int*)  d_in[1];
    const float* w_qs = (const float*)d_in[2];
    const float* w_ks = (const float*)d_in[3];
    const float* w_vs = (const float*)d_in[4];
    const float* w_fc = (const float*)d_in[5];
    const float* ga   = (const float*)d_in[6];
    const float* be   = (const float*)d_in[7];
    float* out = (float*)d_out;

    const int OUT_ELEMS  = M_ * D_;                        // 4194304
    const long long ATTN_ELEMS = (long long)BH_ * S_ * S_; // 134217728
    float* attn_ext = ((long long)out_size >= OUT_ELEMS + ATTN_ELEMS)
                        ? out + OUT_ELEMS : nullptr;

    const int SMEM_ATTN = (8704 + 8704 + 4352 + 4608 + 256 + 128) * 4; // 106 KB
    cudaFuncSetAttribute(k_attn, cudaFuncAttributeMaxDynamicSharedMemorySize, SMEM_ATTN);

    k_proj  <<<dim3(8, 32, 3), 256>>>(qkv, w_qs, w_ks, w_vs);
    k_attn  <<<dim3(16, 32), 256, SMEM_ATTN>>>(mask, attn_ext);
    k_scale <<<BH_ * S_, 256>>>(attn_ext);
    k_fc    <<<dim3(8, 32), 256>>>(qkv, w_fc);
    k_ln    <<<M_, 256>>>(ga, be, out);
}

// round 12
// speedup vs baseline: 1.1970x; 1.1970x over previous
#include <cuda_runtime.h>
#include <cstdint>

// ---------------- problem constants ----------------
#define B_    2
#define S_    2048
#define D_    1024
#define H_    16
#define DK_   64
#define BH_   (B_*H_)        // 32
#define M_    (B_*S_)        // 4096
#define LNEPS 1e-6f
#define INVTEMP 0.125f       // 1/sqrt(64)

// ---------------- device scratch (static; no allocations) ----------------
__device__ float g_q[(size_t)BH_*S_*DK_];
__device__ float g_k[(size_t)BH_*S_*DK_];
__device__ float g_v[(size_t)BH_*S_*DK_];
__device__ float g_o[(size_t)M_*D_];
__device__ float g_fc[(size_t)M_*D_];
__device__ float g_rsum[BH_*S_];
__device__ float g_attn[(size_t)BH_*S_*S_];   // fallback if attn not in d_out

// ---------------- tf32 helpers ----------------
__device__ __forceinline__ uint32_t tf32r(float f){
    uint32_t u; asm("cvt.rna.tf32.f32 %0,%1;" : "=r"(u) : "f"(f)); return u;
}

#define MMA_TF32(c,a,b) \
  asm volatile("mma.sync.aligned.m16n8k8.row.col.f32.tf32.tf32.f32 " \
    "{%0,%1,%2,%3},{%4,%5,%6,%7},{%8,%9},{%0,%1,%2,%3};" \
    : "+f"(c[0]),"+f"(c[1]),"+f"(c[2]),"+f"(c[3]) \
    : "r"(a[0]),"r"(a[1]),"r"(a[2]),"r"(a[3]),"r"(b[0]),"r"(b[1]))

// One 32-deep K-chunk of warp-level MMAs.
// As: [m][AP] m-major tf32; Bs: [32][BP] k-major tf32.
// Warp tile: 32 (m) x NB*8 (n).
template<int NB, int AP, int BP>
__device__ __forceinline__ void mma_chunk(const uint32_t* As, const uint32_t* Bs,
        int wm, int wn, int lane, float (*c)[NB][4])
{
    const int r = lane >> 2, q = lane & 3;
    #pragma unroll
    for (int ks = 0; ks < 4; ks++) {
        const int k0 = ks * 8;
        uint32_t a[2][4], b[NB][2];
        #pragma unroll
        for (int im = 0; im < 2; im++) {
            const uint32_t* ap = As + (size_t)(wm + 16*im + r) * AP + k0 + q;
            a[im][0] = ap[0];      a[im][1] = ap[8*AP];
            a[im][2] = ap[4];      a[im][3] = ap[8*AP + 4];
        }
        #pragma unroll
        for (int jn = 0; jn < NB; jn++) {
            const uint32_t* bp = Bs + (size_t)(k0 + q) * BP + wn + 8*jn + r;
            b[jn][0] = bp[0];      b[jn][1] = bp[4*BP];
        }
        #pragma unroll
        for (int im = 0; im < 2; im++)
            #pragma unroll
            for (int jn = 0; jn < NB; jn++)
                MMA_TF32(c[im][jn], a[im], b[jn]);
    }
}

// ---------------- block reduction (blockDim == 256) ----------------
__device__ __forceinline__ float bred_sum(float v, float* red){
    #pragma unroll
    for (int o = 16; o; o >>= 1) v += __shfl_xor_sync(0xffffffffu, v, o);
    if ((threadIdx.x & 31) == 0) red[threadIdx.x >> 5] = v;
    __syncthreads();
    float r = red[0];
    #pragma unroll
    for (int i = 1; i < 8; i++) r += red[i];
    __syncthreads();
    return r;
}

// =======================================================================
// K1: QKV projections (tf32 MMA, 32-deep chunks, 2 CTA/SM).
// Y = X[4096,1024] @ W[1024,1024].  Output layout: [bh][s][dk].
// =======================================================================
__global__ __launch_bounds__(256)
void k_proj(const float* __restrict__ X,
            const float* __restrict__ Wq,
            const float* __restrict__ Wk,
            const float* __restrict__ Wv)
{
    __shared__ uint32_t As[128*36];
    __shared__ uint32_t Bs[32*136];
    const int z = blockIdx.z;
    const float* W = (z == 0) ? Wq : (z == 1) ? Wk : Wv;
    float* DST     = (z == 0) ? g_q : (z == 1) ? g_k : g_v;
    const int n0 = blockIdx.x * 128, m0 = blockIdx.y * 128;
    const int t = threadIdx.x, lane = t & 31, wid = t >> 5;
    const int wm = (wid & 3) * 32, wn = (wid >> 2) * 64;

    float c[2][8][4];
    #pragma unroll
    for (int i=0;i<2;i++)
        #pragma unroll
        for (int j=0;j<8;j++)
            #pragma unroll
            for (int k=0;k<4;k++) c[i][j][k]=0.f;

    for (int k0 = 0; k0 < 1024; k0 += 32) {
        #pragma unroll
        for (int p = 0; p < 4; p++) {               // A: 128x32
            int f = t + p*256, r = f >> 3, c4 = f & 7;
            float4 v = *(const float4*)&X[(size_t)(m0+r)*1024 + k0 + c4*4];
            uint32_t* d = &As[r*36 + c4*4];
            d[0]=tf32r(v.x); d[1]=tf32r(v.y); d[2]=tf32r(v.z); d[3]=tf32r(v.w);
        }
        #pragma unroll
        for (int p = 0; p < 4; p++) {               // B: 32x128
            int f = t + p*256, r = f >> 5, c4 = f & 31;
            float4 v = *(const float4*)&W[(size_t)(k0+r)*1024 + n0 + c4*4];
            uint32_t* d = &Bs[r*136 + c4*4];
            d[0]=tf32r(v.x); d[1]=tf32r(v.y); d[2]=tf32r(v.z); d[3]=tf32r(v.w);
        }
        __syncthreads();
        mma_chunk<8,36,136>(As, Bs, wm, wn, lane, c);
        __syncthreads();
    }
    const int r = lane >> 2, q4 = lane & 3;
    #pragma unroll
    for (int im = 0; im < 2; im++) {
        #pragma unroll
        for (int jn = 0; jn < 8; jn++) {
            const int n = n0 + wn + 8*jn + 2*q4;
            const int hh = n >> 6, nc = n & 63;
            #pragma unroll
            for (int hr = 0; hr < 2; hr++) {
                const int m = m0 + wm + 16*im + r + 8*hr;
                const int b = m >> 11, s = m & 2047;
                *(float2*)&DST[(((size_t)(b*H_ + hh))*S_ + s)*DK_ + nc] =
                    make_float2(c[im][jn][2*hr], c[im][jn][2*hr+1]);
            }
        }
    }
}

// =======================================================================
// K2: k_attn — single-pass attention (measured-best R7 form):
//   loop: QK^T -> e=exp(masked l) (unnormalized) -> write e + PV mma;
//   row sums accumulate in registers. epilogue: O = acc/sum.
// grid (qtile=16, bh=32), 256 threads.
// =======================================================================
__global__ __launch_bounds__(256)
void k_attn(const int* __restrict__ mask, float* __restrict__ attn_ext)
{
    extern __shared__ uint32_t sh[];
    uint32_t* Qs  = sh;                    // [128][68]      8704 w
    uint32_t* Ps  = sh + 8704;             // [128][68]      8704 w
    uint32_t* Bsb = sh + 17408;            // 2 x [32][72]   4608 w
    uint32_t* Vsb = sh + 22016;            // 2 x [32][72]   4608 w
    float* s_red  = (float*)(sh + 26624);  // [2][128]
    float* s_inv  = s_red + 256;           // [128]

    float* attn = attn_ext ? attn_ext : g_attn;
    const int bh = blockIdx.y, b = bh >> 4, h = bh & 15;
    const int m0 = blockIdx.x * 128;
    const float* Q = g_q + (size_t)bh * S_ * DK_;
    const float* K = g_k + (size_t)bh * S_ * DK_;
    const float* V = g_v + (size_t)bh * S_ * DK_;
    const int t = threadIdx.x, lane = t & 31, wid = t >> 5;
    const int wm = (wid & 3) * 32, wc = wid >> 2, wn = wc * 32;
    const int r8 = lane >> 2, q4 = lane & 3;

    #pragma unroll
    for (int p = 0; p < 8; p++) {          // Q tile 128x64, pitch 68
        int f = t + p*256, rr = f >> 4, c4 = f & 15;
        float4 v = *(const float4*)&Q[(size_t)(m0+rr)*DK_ + c4*4];
        uint32_t* d = &Qs[rr*68 + c4*4];
        d[0]=tf32r(v.x); d[1]=tf32r(v.y); d[2]=tf32r(v.z); d[3]=tf32r(v.w);
    }

    float acc[2][4][4];
    #pragma unroll
    for (int i=0;i<2;i++)
        #pragma unroll
        for (int j=0;j<4;j++)
            #pragma unroll
            for (int k=0;k<4;k++) acc[i][j][k]=0.f;
    float s_acc[4] = {0.f, 0.f, 0.f, 0.f};

    for (int kt = 0; kt < 32; kt++) {
        const int n0 = kt * 64;
        __syncthreads();                   // prev PV mma done (also Qs ready @kt=0)
        #pragma unroll
        for (int p = 0; p < 4; p++) {      // K 64keys x 64dk transposed
            int f = t + p*256, key = f >> 4, c4 = f & 15;
            const int ch = c4 >> 3, colb = (c4 & 7) * 4;
            float4 v = *(const float4*)&K[(size_t)(n0+key)*DK_ + c4*4];
            uint32_t* d = &Bsb[ch*32*72];
            d[(colb+0)*72 + key] = tf32r(v.x);
            d[(colb+1)*72 + key] = tf32r(v.y);
            d[(colb+2)*72 + key] = tf32r(v.z);
            d[(colb+3)*72 + key] = tf32r(v.w);
        }
        #pragma unroll
        for (int p = 0; p < 4; p++) {      // V 64keys x 64 natural
            int f = t + p*256, rr = f >> 4, c4 = f & 15;
            const int ch = rr >> 5;
            float4 v = *(const float4*)&V[(size_t)(n0+rr)*DK_ + c4*4];
            uint32_t* d = &Vsb[ch*32*72 + (rr & 31)*72 + c4*4];
            d[0]=tf32r(v.x); d[1]=tf32r(v.y); d[2]=tf32r(v.z); d[3]=tf32r(v.w);
        }
        __syncthreads();

        float c[2][4][4];
        #pragma unroll
        for (int i=0;i<2;i++)
            #pragma unroll
            for (int j=0;j<4;j++)
                #pragma unroll
                for (int k=0;k<4;k++) c[i][j][k]=0.f;
        mma_chunk<4,68,72>(Qs,      Bsb,         wm, wn, lane, c);
        mma_chunk<4,68,72>(Qs + 32, Bsb + 32*72, wm, wn, lane, c);

        // e = mask ? exp(l) : 0 ; write unnormalized e + stage + row sums
        #pragma unroll
        for (int im = 0; im < 2; im++)
        #pragma unroll
        for (int hr = 0; hr < 2; hr++) {
            const int rowloc = wm + 16*im + 8*hr + r8;
            const int qg = m0 + rowloc;
            const size_t mrow = (size_t)b*S_*S_ + (size_t)qg*S_;
            const size_t arow = ((size_t)bh*S_ + qg) * S_;
            float s = 0.f;
            #pragma unroll
            for (int jn = 0; jn < 4; jn++) {
                const int colloc = wn + 8*jn + 2*q4;
                const int col = n0 + colloc;
                const int2 mk = *(const int2*)&mask[mrow + col];
                const float ex = mk.x ? __expf(c[im][jn][2*hr]   * INVTEMP) : 0.f;
                const float ey = mk.y ? __expf(c[im][jn][2*hr+1] * INVTEMP) : 0.f;
                s += ex + ey;
                *(float2*)&attn[arow + col] = make_float2(ex, ey);
                Ps[rowloc*68 + colloc]     = tf32r(ex);
                Ps[rowloc*68 + colloc + 1] = tf32r(ey);
            }
            s_acc[im*2 + hr] += s;
        }
        __syncthreads();

        mma_chunk<4,68,72>(Ps,      Vsb,         wm, wn, lane, acc);
        mma_chunk<4,68,72>(Ps + 32, Vsb + 32*72, wm, wn, lane, acc);
    }

    // row-sum reduction: q4 lanes -> warp-column partials -> total
    #pragma unroll
    for (int im = 0; im < 2; im++)
    #pragma unroll
    for (int hr = 0; hr < 2; hr++) {
        const int rowloc = wm + 16*im + 8*hr + r8;
        float s = s_acc[im*2 + hr];
        s += __shfl_xor_sync(0xffffffffu, s, 1);
        s += __shfl_xor_sync(0xffffffffu, s, 2);
        if (q4 == 0) s_red[wc*128 + rowloc] = s;
    }
    __syncthreads();
    if (t < 128) {
        const float tot = s_red[t] + s_red[128 + t];
        g_rsum[bh*S_ + m0 + t] = tot;
        s_inv[t] = 1.f / tot;
    }
    __syncthreads();

    // epilogue: O = acc * inv, merged [b*S+q][h*64+n]
    #pragma unroll
    for (int im = 0; im < 2; im++)
    #pragma unroll
    for (int hr = 0; hr < 2; hr++) {
        const int rowloc = wm + 16*im + 8*hr + r8;
        const int qg = m0 + rowloc;
        const float inv = s_inv[rowloc];
        float* orow = &g_o[(size_t)(b*S_ + qg)*D_ + h*DK_];
        #pragma unroll
        for (int jn = 0; jn < 4; jn++) {
            const int n = wn + 8*jn + 2*q4;
            *(float2*)&orow[n] = make_float2(acc[im][jn][2*hr] * inv,
                                             acc[im][jn][2*hr+1] * inv);
        }
    }
}

// =======================================================================
// K3: k_scale — attn[row][*] *= 1/rowsum. Dedicated streaming kernel,
// launched on a side stream concurrent with k_fc -> k_ln (independent).
// =======================================================================
__global__ __launch_bounds__(256)
void k_scale(float* __restrict__ attn_ext)
{
    float* attn = attn_ext ? attn_ext : g_attn;
    const int row = blockIdx.x;            // 0 .. BH_*S_-1
    const float inv = 1.f / g_rsum[row];
    float4* p = (float4*)(attn + (size_t)row * S_);
    const int t = threadIdx.x;
    #pragma unroll
    for (int u = 0; u < 2; u++) {
        float4 v = p[t + 256*u];
        v.x *= inv; v.y *= inv; v.z *= inv; v.w *= inv;
        p[t + 256*u] = v;
    }
}

// =======================================================================
// K4: fc = O[4096,1024] @ w_fc[1024,1024] + residual (tf32)
// =======================================================================
__global__ __launch_bounds__(256)
void k_fc(const float* __restrict__ X, const float* __restrict__ W)
{
    __shared__ uint32_t As[128*36];
    __shared__ uint32_t Bs[32*136];
    const int n0 = blockIdx.x * 128, m0 = blockIdx.y * 128;
    const int t = threadIdx.x, lane = t & 31, wid = t >> 5;
    const int wm = (wid & 3) * 32, wn = (wid >> 2) * 64;

    float c[2][8][4];
    #pragma unroll
    for (int i=0;i<2;i++)
        #pragma unroll
        for (int j=0;j<8;j++)
            #pragma unroll
            for (int k=0;k<4;k++) c[i][j][k]=0.f;

    for (int k0 = 0; k0 < 1024; k0 += 32) {
        #pragma unroll
        for (int p = 0; p < 4; p++) {
            int f = t + p*256, r = f >> 3, c4 = f & 7;
            float4 v = *(const float4*)&g_o[(size_t)(m0+r)*1024 + k0 + c4*4];
            uint32_t* d = &As[r*36 + c4*4];
            d[0]=tf32r(v.x); d[1]=tf32r(v.y); d[2]=tf32r(v.z); d[3]=tf32r(v.w);
        }
        #pragma unroll
        for (int p = 0; p < 4; p++) {
            int f = t + p*256, r = f >> 5, c4 = f & 31;
            float4 v = *(const float4*)&W[(size_t)(k0+r)*1024 + n0 + c4*4];
            uint32_t* d = &Bs[r*136 + c4*4];
            d[0]=tf32r(v.x); d[1]=tf32r(v.y); d[2]=tf32r(v.z); d[3]=tf32r(v.w);
        }
        __syncthreads();
        mma_chunk<8,36,136>(As, Bs, wm, wn, lane, c);
        __syncthreads();
    }
    const int r = lane >> 2, q4 = lane & 3;
    #pragma unroll
    for (int im = 0; im < 2; im++) {
        #pragma unroll
        for (int hr = 0; hr < 2; hr++) {
            const int m = m0 + wm + 16*im + r + 8*hr;
            #pragma unroll
            for (int jn = 0; jn < 8; jn++) {
                const int n = n0 + wn + 8*jn + 2*q4;
                const float2 res = *(const float2*)&X[(size_t)m*D_ + n];
                *(float2*)&g_fc[(size_t)m*D_ + n] =
                    make_float2(c[im][jn][2*hr] + res.x, c[im][jn][2*hr+1] + res.y);
            }
        }
    }
}

// =======================================================================
// K5: LayerNorm over last dim (1024), write final out region.
// =======================================================================
__global__ __launch_bounds__(256)
void k_ln(const float* __restrict__ gamma, const float* __restrict__ beta,
          float* __restrict__ out)
{
    __shared__ float red[8];
    const int m = blockIdx.x, t = threadIdx.x;
    const float* x = g_fc + (size_t)m * D_;
    float v[4];
    #pragma unroll
    for (int u = 0; u < 4; u++) v[u] = x[t + 256 * u];
    float s = v[0] + v[1] + v[2] + v[3];
    const float mu = bred_sum(s, red) * (1.0f / D_);
    float d2 = 0.f;
    #pragma unroll
    for (int u = 0; u < 4; u++) { float d = v[u] - mu; d2 += d * d; }
    const float var = bred_sum(d2, red) * (1.0f / D_);
    const float rstd = rsqrtf(var + LNEPS);
    #pragma unroll
    for (int u = 0; u < 4; u++) {
        const int c = t + 256 * u;
        out[(size_t)m * D_ + c] = (v[u] - mu) * rstd * gamma[c] + beta[c];
    }
}

// =======================================================================
extern "C" void kernel_launch(void* const* d_in, const int* in_sizes, int n_in,
                              void* d_out, int out_size)
{
    (void)in_sizes; (void)n_in;
    const float* qkv  = (const float*)d_in[0];
    const int*   mask = (const int*)  d_in[1];
    const float* w_qs = (const float*)d_in[2];
    const float* w_ks = (const float*)d_in[3];
    const float* w_vs = (const float*)d_in[4];
    const float* w_fc = (const float*)d_in[5];
    const float* ga   = (const float*)d_in[6];
    const float* be   = (const float*)d_in[7];
    float* out = (float*)d_out;

    const int OUT_ELEMS  = M_ * D_;                        // 4194304
    const long long ATTN_ELEMS = (long long)BH_ * S_ * S_; // 134217728
    float* attn_ext = ((long long)out_size >= OUT_ELEMS + ATTN_ELEMS)
                        ? out + OUT_ELEMS : nullptr;

    // one-time host resources (created on the first, non-captured call;
    // no device memory involved; identical work enqueued on every call)
    static cudaStream_t s2 = nullptr;
    static cudaEvent_t ev_fork = nullptr, ev_join = nullptr;
    static bool init_tried = false, fork_ok = false;
    if (!init_tried) {
        init_tried = true;
        fork_ok = (cudaStreamCreateWithFlags(&s2, cudaStreamNonBlocking) == cudaSuccess)
               && (cudaEventCreateWithFlags(&ev_fork, cudaEventDisableTiming) == cudaSuccess)
               && (cudaEventCreateWithFlags(&ev_join, cudaEventDisableTiming) == cudaSuccess);
    }

    const int SMEM_ATTN = (8704 + 8704 + 4608 + 4608 + 256 + 128) * 4; // 108032 B
    cudaFuncSetAttribute(k_attn, cudaFuncAttributeMaxDynamicSharedMemorySize, SMEM_ATTN);

    k_proj <<<dim3(8, 32, 3), 256>>>(qkv, w_qs, w_ks, w_vs);
    k_attn <<<dim3(16, 32), 256, SMEM_ATTN>>>(mask, attn_ext);

    if (fork_ok) {
        // fork: k_scale (bandwidth-bound) overlaps with k_fc->k_ln (tensor-bound)
        cudaEventRecord(ev_fork, 0);
        cudaStreamWaitEvent(s2, ev_fork, 0);
        k_scale <<<BH_ * S_, 256, 0, s2>>>(attn_ext);
        cudaEventRecord(ev_join, s2);

        k_fc   <<<dim3(8, 32), 256>>>(qkv, w_fc);
        k_ln   <<<M_, 256>>>(ga, be, out);

        // join: everything back on the main stream before return
        cudaStreamWaitEvent(0, ev_join, 0);
    } else {
        // fallback: fully serialized (exactly the measured R7 pipeline)
        k_scale <<<BH_ * S_, 256>>>(attn_ext);
        k_fc    <<<dim3(8, 32), 256>>>(qkv, w_fc);
        k_ln    <<<M_, 256>>>(ga, be, out);
    }
}

// round 13
// speedup vs baseline: 1.2047x; 1.0064x over previous
#include <cuda_runtime.h>
#include <cstdint>

// ---------------- problem constants ----------------
#define B_    2
#define S_    2048
#define D_    1024
#define H_    16
#define DK_   64
#define BH_   (B_*H_)        // 32
#define M_    (B_*S_)        // 4096
#define LNEPS 1e-6f
#define INVTEMP 0.125f       // 1/sqrt(64)

// ---------------- device scratch (static; no allocations) ----------------
__device__ float g_q[(size_t)BH_*S_*DK_];
__device__ float g_k[(size_t)BH_*S_*DK_];
__device__ float g_v[(size_t)BH_*S_*DK_];
__device__ float g_o[(size_t)M_*D_];
__device__ float g_fc[(size_t)M_*D_];
__device__ float g_rsum[BH_*S_];
__device__ float g_attn[(size_t)BH_*S_*S_];   // fallback if attn not in d_out

// ---------------- tf32 helpers ----------------
__device__ __forceinline__ uint32_t tf32r(float f){
    uint32_t u; asm("cvt.rna.tf32.f32 %0,%1;" : "=r"(u) : "f"(f)); return u;
}

#define MMA_TF32(c,a,b) \
  asm volatile("mma.sync.aligned.m16n8k8.row.col.f32.tf32.tf32.f32 " \
    "{%0,%1,%2,%3},{%4,%5,%6,%7},{%8,%9},{%0,%1,%2,%3};" \
    : "+f"(c[0]),"+f"(c[1]),"+f"(c[2]),"+f"(c[3]) \
    : "r"(a[0]),"r"(a[1]),"r"(a[2]),"r"(a[3]),"r"(b[0]),"r"(b[1]))

// One 32-deep K-chunk of warp-level MMAs (dense GEMM kernels).
// As: [m][AP] m-major tf32; Bs: [32][BP] k-major tf32.
// Warp tile: 32 (m) x NB*8 (n).
template<int NB, int AP, int BP>
__device__ __forceinline__ void mma_chunk(const uint32_t* As, const uint32_t* Bs,
        int wm, int wn, int lane, float (*c)[NB][4])
{
    const int r = lane >> 2, q = lane & 3;
    #pragma unroll
    for (int ks = 0; ks < 4; ks++) {
        const int k0 = ks * 8;
        uint32_t a[2][4], b[NB][2];
        #pragma unroll
        for (int im = 0; im < 2; im++) {
            const uint32_t* ap = As + (size_t)(wm + 16*im + r) * AP + k0 + q;
            a[im][0] = ap[0];      a[im][1] = ap[8*AP];
            a[im][2] = ap[4];      a[im][3] = ap[8*AP + 4];
        }
        #pragma unroll
        for (int jn = 0; jn < NB; jn++) {
            const uint32_t* bp = Bs + (size_t)(k0 + q) * BP + wn + 8*jn + r;
            b[jn][0] = bp[0];      b[jn][1] = bp[4*BP];
        }
        #pragma unroll
        for (int im = 0; im < 2; im++)
            #pragma unroll
            for (int jn = 0; jn < NB; jn++)
                MMA_TF32(c[im][jn], a[im], b[jn]);
    }
}

// ---------------- block reduction (blockDim == 256) ----------------
__device__ __forceinline__ float bred_sum(float v, float* red){
    #pragma unroll
    for (int o = 16; o; o >>= 1) v += __shfl_xor_sync(0xffffffffu, v, o);
    if ((threadIdx.x & 31) == 0) red[threadIdx.x >> 5] = v;
    __syncthreads();
    float r = red[0];
    #pragma unroll
    for (int i = 1; i < 8; i++) r += red[i];
    __syncthreads();
    return r;
}

// =======================================================================
// K1: QKV projections (tf32 MMA, 32-deep chunks, 2 CTA/SM).
// Y = X[4096,1024] @ W[1024,1024].  Output layout: [bh][s][dk].
// =======================================================================
__global__ __launch_bounds__(256)
void k_proj(const float* __restrict__ X,
            const float* __restrict__ Wq,
            const float* __restrict__ Wk,
            const float* __restrict__ Wv)
{
    __shared__ uint32_t As[128*36];
    __shared__ uint32_t Bs[32*136];
    const int z = blockIdx.z;
    const float* W = (z == 0) ? Wq : (z == 1) ? Wk : Wv;
    float* DST     = (z == 0) ? g_q : (z == 1) ? g_k : g_v;
    const int n0 = blockIdx.x * 128, m0 = blockIdx.y * 128;
    const int t = threadIdx.x, lane = t & 31, wid = t >> 5;
    const int wm = (wid & 3) * 32, wn = (wid >> 2) * 64;

    float c[2][8][4];
    #pragma unroll
    for (int i=0;i<2;i++)
        #pragma unroll
        for (int j=0;j<8;j++)
            #pragma unroll
            for (int k=0;k<4;k++) c[i][j][k]=0.f;

    for (int k0 = 0; k0 < 1024; k0 += 32) {
        #pragma unroll
        for (int p = 0; p < 4; p++) {               // A: 128x32
            int f = t + p*256, r = f >> 3, c4 = f & 7;
            float4 v = *(const float4*)&X[(size_t)(m0+r)*1024 + k0 + c4*4];
            uint32_t* d = &As[r*36 + c4*4];
            d[0]=tf32r(v.x); d[1]=tf32r(v.y); d[2]=tf32r(v.z); d[3]=tf32r(v.w);
        }
        #pragma unroll
        for (int p = 0; p < 4; p++) {               // B: 32x128
            int f = t + p*256, r = f >> 5, c4 = f & 31;
            float4 v = *(const float4*)&W[(size_t)(k0+r)*1024 + n0 + c4*4];
            uint32_t* d = &Bs[r*136 + c4*4];
            d[0]=tf32r(v.x); d[1]=tf32r(v.y); d[2]=tf32r(v.z); d[3]=tf32r(v.w);
        }
        __syncthreads();
        mma_chunk<8,36,136>(As, Bs, wm, wn, lane, c);
        __syncthreads();
    }
    const int r = lane >> 2, q4 = lane & 3;
    #pragma unroll
    for (int im = 0; im < 2; im++) {
        #pragma unroll
        for (int jn = 0; jn < 8; jn++) {
            const int n = n0 + wn + 8*jn + 2*q4;
            const int hh = n >> 6, nc = n & 63;
            #pragma unroll
            for (int hr = 0; hr < 2; hr++) {
                const int m = m0 + wm + 16*im + r + 8*hr;
                const int b = m >> 11, s = m & 2047;
                *(float2*)&DST[(((size_t)(b*H_ + hh))*S_ + s)*DK_ + nc] =
                    make_float2(c[im][jn][2*hr], c[im][jn][2*hr+1]);
            }
        }
    }
}

// =======================================================================
// K2: k_attn — single-pass attention, FA2-style m-only warp tiling.
// Each of 8 warps owns 16 q-rows x ALL 64 keys of the tile:
//   QK mma (P in regs) -> mask/exp/gmem-write/rowsum (C layout)
//   -> quad-shuffle C->A fragments -> PV mma.
// No Ps smem, 2 syncs/iter, no end barriers (row sums quad-local).
// grid (qtile=16, bh=32), 256 threads.
// =======================================================================
__global__ __launch_bounds__(256)
void k_attn(const int* __restrict__ mask, float* __restrict__ attn_ext)
{
    extern __shared__ uint32_t sh[];
    uint32_t* Qs  = sh;                    // [128][68]      8704 w
    uint32_t* Ksb = sh + 8704;             // 2 x [32][72]   4608 w (K^T: [dk][key])
    uint32_t* Vsb = sh + 13312;            // 2 x [32][72]   4608 w ([key][dv])

    float* attn = attn_ext ? attn_ext : g_attn;
    const int bh = blockIdx.y, b = bh >> 4, h = bh & 15;
    const int m0 = blockIdx.x * 128;
    const float* Q = g_q + (size_t)bh * S_ * DK_;
    const float* K = g_k + (size_t)bh * S_ * DK_;
    const float* V = g_v + (size_t)bh * S_ * DK_;
    const int t = threadIdx.x, lane = t & 31, wid = t >> 5;
    const int wm = wid * 16;               // warp owns rows [wm, wm+16)
    const int r8 = lane >> 2, q4 = lane & 3;

    #pragma unroll
    for (int p = 0; p < 8; p++) {          // Q tile 128x64, pitch 68
        int f = t + p*256, rr = f >> 4, c4 = f & 15;
        float4 v = *(const float4*)&Q[(size_t)(m0+rr)*DK_ + c4*4];
        uint32_t* d = &Qs[rr*68 + c4*4];
        d[0]=tf32r(v.x); d[1]=tf32r(v.y); d[2]=tf32r(v.z); d[3]=tf32r(v.w);
    }

    float acc[8][4];
    #pragma unroll
    for (int j=0;j<8;j++)
        #pragma unroll
        for (int k=0;k<4;k++) acc[j][k]=0.f;
    float s0 = 0.f, s1 = 0.f;              // row sums for rows wm+r8, wm+8+r8

    // global row/mask bases for this thread's two rows
    const int qg0 = m0 + wm + r8, qg1 = qg0 + 8;
    const size_t mrow0 = (size_t)b*S_*S_ + (size_t)qg0*S_;
    const size_t mrow1 = (size_t)b*S_*S_ + (size_t)qg1*S_;
    const size_t arow0 = ((size_t)bh*S_ + qg0) * S_;
    const size_t arow1 = ((size_t)bh*S_ + qg1) * S_;

    const int quad_base = lane & ~3;
    const int srcA = quad_base | (q4 >> 1);       // holds dest col q4
    const int srcB = srcA + 2;                    // holds dest col q4+4
    const bool oddq = (q4 & 1);

    for (int kt = 0; kt < 32; kt++) {
        const int n0 = kt * 64;
        __syncthreads();                   // prev iter's mma reads done
        #pragma unroll
        for (int p = 0; p < 4; p++) {      // K 64keys x 64dk -> transposed [dk][key]
            int f = t + p*256, key = f >> 4, c4 = f & 15;
            const int ch = c4 >> 3, colb = (c4 & 7) * 4;
            float4 v = *(const float4*)&K[(size_t)(n0+key)*DK_ + c4*4];
            uint32_t* d = &Ksb[ch*32*72];
            d[(colb+0)*72 + key] = tf32r(v.x);
            d[(colb+1)*72 + key] = tf32r(v.y);
            d[(colb+2)*72 + key] = tf32r(v.z);
            d[(colb+3)*72 + key] = tf32r(v.w);
        }
        #pragma unroll
        for (int p = 0; p < 4; p++) {      // V 64keys x 64 natural [key][dv]
            int f = t + p*256, rr = f >> 4, c4 = f & 15;
            const int ch = rr >> 5;
            float4 v = *(const float4*)&V[(size_t)(n0+rr)*DK_ + c4*4];
            uint32_t* d = &Vsb[ch*32*72 + (rr & 31)*72 + c4*4];
            d[0]=tf32r(v.x); d[1]=tf32r(v.y); d[2]=tf32r(v.z); d[3]=tf32r(v.w);
        }
        __syncthreads();

        // ---- QK^T: c[128 rows (warp: 16)][64 keys] ----
        float c[8][4];
        #pragma unroll
        for (int j=0;j<8;j++)
            #pragma unroll
            for (int k=0;k<4;k++) c[j][k]=0.f;
        #pragma unroll
        for (int ks = 0; ks < 8; ks++) {   // k (dk) chunks of 8
            const uint32_t* ap = Qs + (size_t)(wm + r8)*68 + 8*ks + q4;
            uint32_t a[4] = { ap[0], ap[8*68], ap[4], ap[8*68 + 4] };
            const uint32_t* Bb = Ksb + (ks >= 4 ? 32*72 : 0) + (size_t)(8*(ks & 3) + q4)*72;
            #pragma unroll
            for (int jn = 0; jn < 8; jn++) {
                uint32_t bfr[2] = { Bb[8*jn + r8], Bb[4*72 + 8*jn + r8] };
                MMA_TF32(c[jn], a, bfr);
            }
        }

        // ---- mask + exp + gmem write + row sums (C layout) ----
        #pragma unroll
        for (int jn = 0; jn < 8; jn++) {
            const int col = n0 + 8*jn + 2*q4;
            const int2 mk0 = *(const int2*)&mask[mrow0 + col];
            const int2 mk1 = *(const int2*)&mask[mrow1 + col];
            const float p0 = mk0.x ? __expf(c[jn][0] * INVTEMP) : 0.f;
            const float p1 = mk0.y ? __expf(c[jn][1] * INVTEMP) : 0.f;
            const float p2 = mk1.x ? __expf(c[jn][2] * INVTEMP) : 0.f;
            const float p3 = mk1.y ? __expf(c[jn][3] * INVTEMP) : 0.f;
            *(float2*)&attn[arow0 + col] = make_float2(p0, p1);
            *(float2*)&attn[arow1 + col] = make_float2(p2, p3);
            s0 += p0 + p1;  s1 += p2 + p3;
            c[jn][0] = p0; c[jn][1] = p1; c[jn][2] = p2; c[jn][3] = p3;
        }

        // ---- quad-shuffle C->A fragments, PV mma per 8-key chunk ----
        #pragma unroll
        for (int jb = 0; jb < 8; jb++) {   // key chunk: keys 8*jb .. 8*jb+7
            const float lo0 = __shfl_sync(0xffffffffu, c[jb][0], srcA);
            const float hi0 = __shfl_sync(0xffffffffu, c[jb][1], srcA);
            const float lo1 = __shfl_sync(0xffffffffu, c[jb][2], srcA);
            const float hi1 = __shfl_sync(0xffffffffu, c[jb][3], srcA);
            const float lo2 = __shfl_sync(0xffffffffu, c[jb][0], srcB);
            const float hi2 = __shfl_sync(0xffffffffu, c[jb][1], srcB);
            const float lo3 = __shfl_sync(0xffffffffu, c[jb][2], srcB);
            const float hi3 = __shfl_sync(0xffffffffu, c[jb][3], srcB);
            uint32_t a[4];
            a[0] = tf32r(oddq ? hi0 : lo0);   // (row r,   key q4)
            a[1] = tf32r(oddq ? hi1 : lo1);   // (row r+8, key q4)
            a[2] = tf32r(oddq ? hi2 : lo2);   // (row r,   key q4+4)
            a[3] = tf32r(oddq ? hi3 : lo3);   // (row r+8, key q4+4)
            const uint32_t* Vb = Vsb + (jb >= 4 ? 32*72 : 0) + (size_t)(8*(jb & 3) + q4)*72;
            #pragma unroll
            for (int jn = 0; jn < 8; jn++) {
                uint32_t bfr[2] = { Vb[8*jn + r8], Vb[4*72 + 8*jn + r8] };
                MMA_TF32(acc[jn], a, bfr);
            }
        }
    }

    // ---- row sums complete within quad; no barriers needed ----
    s0 += __shfl_xor_sync(0xffffffffu, s0, 1);
    s0 += __shfl_xor_sync(0xffffffffu, s0, 2);
    s1 += __shfl_xor_sync(0xffffffffu, s1, 1);
    s1 += __shfl_xor_sync(0xffffffffu, s1, 2);
    if (q4 == 0) {
        g_rsum[bh*S_ + qg0] = s0;
        g_rsum[bh*S_ + qg1] = s1;
    }
    const float inv0 = 1.f / s0, inv1 = 1.f / s1;

    // ---- epilogue: O merged [b*S+q][h*64+n] ----
    float* orow0 = &g_o[(size_t)(b*S_ + qg0)*D_ + h*DK_];
    float* orow1 = &g_o[(size_t)(b*S_ + qg1)*D_ + h*DK_];
    #pragma unroll
    for (int jn = 0; jn < 8; jn++) {
        const int n = 8*jn + 2*q4;
        *(float2*)&orow0[n] = make_float2(acc[jn][0] * inv0, acc[jn][1] * inv0);
        *(float2*)&orow1[n] = make_float2(acc[jn][2] * inv1, acc[jn][3] * inv1);
    }
}

// =======================================================================
// K3: k_scale — attn[row][*] *= 1/rowsum. Dedicated streaming kernel.
// =======================================================================
__global__ __launch_bounds__(256)
void k_scale(float* __restrict__ attn_ext)
{
    float* attn = attn_ext ? attn_ext : g_attn;
    const int row = blockIdx.x;            // 0 .. BH_*S_-1
    const float inv = 1.f / g_rsum[row];
    float4* p = (float4*)(attn + (size_t)row * S_);
    const int t = threadIdx.x;
    #pragma unroll
    for (int u = 0; u < 2; u++) {
        float4 v = p[t + 256*u];
        v.x *= inv; v.y *= inv; v.z *= inv; v.w *= inv;
        p[t + 256*u] = v;
    }
}

// =======================================================================
// K4: fc = O[4096,1024] @ w_fc[1024,1024] + residual (tf32)
// =======================================================================
__global__ __launch_bounds__(256)
void k_fc(const float* __restrict__ X, const float* __restrict__ W)
{
    __shared__ uint32_t As[128*36];
    __shared__ uint32_t Bs[32*136];
    const int n0 = blockIdx.x * 128, m0 = blockIdx.y * 128;
    const int t = threadIdx.x, lane = t & 31, wid = t >> 5;
    const int wm = (wid & 3) * 32, wn = (wid >> 2) * 64;

    float c[2][8][4];
    #pragma unroll
    for (int i=0;i<2;i++)
        #pragma unroll
        for (int j=0;j<8;j++)
            #pragma unroll
            for (int k=0;k<4;k++) c[i][j][k]=0.f;

    for (int k0 = 0; k0 < 1024; k0 += 32) {
        #pragma unroll
        for (int p = 0; p < 4; p++) {
            int f = t + p*256, r = f >> 3, c4 = f & 7;
            float4 v = *(const float4*)&g_o[(size_t)(m0+r)*1024 + k0 + c4*4];
            uint32_t* d = &As[r*36 + c4*4];
            d[0]=tf32r(v.x); d[1]=tf32r(v.y); d[2]=tf32r(v.z); d[3]=tf32r(v.w);
        }
        #pragma unroll
        for (int p = 0; p < 4; p++) {
            int f = t + p*256, r = f >> 5, c4 = f & 31;
            float4 v = *(const float4*)&W[(size_t)(k0+r)*1024 + n0 + c4*4];
            uint32_t* d = &Bs[r*136 + c4*4];
            d[0]=tf32r(v.x); d[1]=tf32r(v.y); d[2]=tf32r(v.z); d[3]=tf32r(v.w);
        }
        __syncthreads();
        mma_chunk<8,36,136>(As, Bs, wm, wn, lane, c);
        __syncthreads();
    }
    const int r = lane >> 2, q4 = lane & 3;
    #pragma unroll
    for (int im = 0; im < 2; im++) {
        #pragma unroll
        for (int hr = 0; hr < 2; hr++) {
            const int m = m0 + wm + 16*im + r + 8*hr;
            #pragma unroll
            for (int jn = 0; jn < 8; jn++) {
                const int n = n0 + wn + 8*jn + 2*q4;
                const float2 res = *(const float2*)&X[(size_t)m*D_ + n];
                *(float2*)&g_fc[(size_t)m*D_ + n] =
                    make_float2(c[im][jn][2*hr] + res.x, c[im][jn][2*hr+1] + res.y);
            }
        }
    }
}

// =======================================================================
// K5: LayerNorm over last dim (1024), write final out region.
// =======================================================================
__global__ __launch_bounds__(256)
void k_ln(const float* __restrict__ gamma, const float* __restrict__ beta,
          float* __restrict__ out)
{
    __shared__ float red[8];
    const int m = blockIdx.x, t = threadIdx.x;
    const float* x = g_fc + (size_t)m * D_;
    float v[4];
    #pragma unroll
    for (int u = 0; u < 4; u++) v[u] = x[t + 256 * u];
    float s = v[0] + v[1] + v[2] + v[3];
    const float mu = bred_sum(s, red) * (1.0f / D_);
    float d2 = 0.f;
    #pragma unroll
    for (int u = 0; u < 4; u++) { float d = v[u] - mu; d2 += d * d; }
    const float var = bred_sum(d2, red) * (1.0f / D_);
    const float rstd = rsqrtf(var + LNEPS);
    #pragma unroll
    for (int u = 0; u < 4; u++) {
        const int c = t + 256 * u;
        out[(size_t)m * D_ + c] = (v[u] - mu) * rstd * gamma[c] + beta[c];
    }
}

// =======================================================================
extern "C" void kernel_launch(void* const* d_in, const int* in_sizes, int n_in,
                              void* d_out, int out_size)
{
    (void)in_sizes; (void)n_in;
    const float* qkv  = (const float*)d_in[0];
    const int*   mask = (const int*)  d_in[1];
    const float* w_qs = (const float*)d_in[2];
    const float* w_ks = (const float*)d_in[3];
    const float* w_vs = (const float*)d_in[4];
    const float* w_fc = (const float*)d_in[5];
    const float* ga   = (const float*)d_in[6];
    const float* be   = (const float*)d_in[7];
    float* out = (float*)d_out;

    const int OUT_ELEMS  = M_ * D_;                        // 4194304
    const long long ATTN_ELEMS = (long long)BH_ * S_ * S_; // 134217728
    float* attn_ext = ((long long)out_size >= OUT_ELEMS + ATTN_ELEMS)
                        ? out + OUT_ELEMS : nullptr;

    const int SMEM_ATTN = (8704 + 4608 + 4608) * 4;        // 71680 B
    cudaFuncSetAttribute(k_attn, cudaFuncAttributeMaxDynamicSharedMemorySize, SMEM_ATTN);

    k_proj  <<<dim3(8, 32, 3), 256>>>(qkv, w_qs, w_ks, w_vs);
    k_attn  <<<dim3(16, 32), 256, SMEM_ATTN>>>(mask, attn_ext);
    k_scale <<<BH_ * S_, 256>>>(attn_ext);
    k_fc    <<<dim3(8, 32), 256>>>(qkv, w_fc);
    k_ln    <<<M_, 256>>>(ga, be, out);
}

// round 14
// speedup vs baseline: 1.2178x; 1.0109x over previous
#include <cuda_runtime.h>
#include <cstdint>

// ---------------- problem constants ----------------
#define B_    2
#define S_    2048
#define D_    1024
#define H_    16
#define DK_   64
#define BH_   (B_*H_)        // 32
#define M_    (B_*S_)        // 4096
#define LNEPS 1e-6f
#define INVTEMP 0.125f       // 1/sqrt(64)

// ---------------- device scratch (static; no allocations) ----------------
__device__ float g_q[(size_t)BH_*S_*DK_];
__device__ float g_k[(size_t)BH_*S_*DK_];
__device__ float g_v[(size_t)BH_*S_*DK_];
__device__ float g_o[(size_t)M_*D_];
__device__ float g_fc[(size_t)M_*D_];
__device__ float g_rsum[BH_*S_];
__device__ float g_attn[(size_t)BH_*S_*S_];   // fallback if attn not in d_out

// ---------------- tf32 helpers ----------------
__device__ __forceinline__ uint32_t tf32r(float f){
    uint32_t u; asm("cvt.rna.tf32.f32 %0,%1;" : "=r"(u) : "f"(f)); return u;
}

#define MMA_TF32(c,a,b) \
  asm volatile("mma.sync.aligned.m16n8k8.row.col.f32.tf32.tf32.f32 " \
    "{%0,%1,%2,%3},{%4,%5,%6,%7},{%8,%9},{%0,%1,%2,%3};" \
    : "+f"(c[0]),"+f"(c[1]),"+f"(c[2]),"+f"(c[3]) \
    : "r"(a[0]),"r"(a[1]),"r"(a[2]),"r"(a[3]),"r"(b[0]),"r"(b[1]))

// One 32-deep K-chunk of warp-level MMAs (dense GEMM kernels).
// As: [m][AP] m-major tf32; Bs: [32][BP] k-major tf32.
// Warp tile: 32 (m) x NB*8 (n).
template<int NB, int AP, int BP>
__device__ __forceinline__ void mma_chunk(const uint32_t* As, const uint32_t* Bs,
        int wm, int wn, int lane, float (*c)[NB][4])
{
    const int r = lane >> 2, q = lane & 3;
    #pragma unroll
    for (int ks = 0; ks < 4; ks++) {
        const int k0 = ks * 8;
        uint32_t a[2][4], b[NB][2];
        #pragma unroll
        for (int im = 0; im < 2; im++) {
            const uint32_t* ap = As + (size_t)(wm + 16*im + r) * AP + k0 + q;
            a[im][0] = ap[0];      a[im][1] = ap[8*AP];
            a[im][2] = ap[4];      a[im][3] = ap[8*AP + 4];
        }
        #pragma unroll
        for (int jn = 0; jn < NB; jn++) {
            const uint32_t* bp = Bs + (size_t)(k0 + q) * BP + wn + 8*jn + r;
            b[jn][0] = bp[0];      b[jn][1] = bp[4*BP];
        }
        #pragma unroll
        for (int im = 0; im < 2; im++)
            #pragma unroll
            for (int jn = 0; jn < NB; jn++)
                MMA_TF32(c[im][jn], a[im], b[jn]);
    }
}

// ---------------- block reduction (blockDim == 256) ----------------
__device__ __forceinline__ float bred_sum(float v, float* red){
    #pragma unroll
    for (int o = 16; o; o >>= 1) v += __shfl_xor_sync(0xffffffffu, v, o);
    if ((threadIdx.x & 31) == 0) red[threadIdx.x >> 5] = v;
    __syncthreads();
    float r = red[0];
    #pragma unroll
    for (int i = 1; i < 8; i++) r += red[i];
    __syncthreads();
    return r;
}

// =======================================================================
// K1: QKV projections (tf32 MMA, 32-deep chunks, 2 CTA/SM).
// Y = X[4096,1024] @ W[1024,1024].  Output layout: [bh][s][dk].
// =======================================================================
__global__ __launch_bounds__(256)
void k_proj(const float* __restrict__ X,
            const float* __restrict__ Wq,
            const float* __restrict__ Wk,
            const float* __restrict__ Wv)
{
    __shared__ uint32_t As[128*36];
    __shared__ uint32_t Bs[32*136];
    const int z = blockIdx.z;
    const float* W = (z == 0) ? Wq : (z == 1) ? Wk : Wv;
    float* DST     = (z == 0) ? g_q : (z == 1) ? g_k : g_v;
    const int n0 = blockIdx.x * 128, m0 = blockIdx.y * 128;
    const int t = threadIdx.x, lane = t & 31, wid = t >> 5;
    const int wm = (wid & 3) * 32, wn = (wid >> 2) * 64;

    float c[2][8][4];
    #pragma unroll
    for (int i=0;i<2;i++)
        #pragma unroll
        for (int j=0;j<8;j++)
            #pragma unroll
            for (int k=0;k<4;k++) c[i][j][k]=0.f;

    for (int k0 = 0; k0 < 1024; k0 += 32) {
        #pragma unroll
        for (int p = 0; p < 4; p++) {               // A: 128x32
            int f = t + p*256, r = f >> 3, c4 = f & 7;
            float4 v = *(const float4*)&X[(size_t)(m0+r)*1024 + k0 + c4*4];
            uint32_t* d = &As[r*36 + c4*4];
            d[0]=tf32r(v.x); d[1]=tf32r(v.y); d[2]=tf32r(v.z); d[3]=tf32r(v.w);
        }
        #pragma unroll
        for (int p = 0; p < 4; p++) {               // B: 32x128
            int f = t + p*256, r = f >> 5, c4 = f & 31;
            float4 v = *(const float4*)&W[(size_t)(k0+r)*1024 + n0 + c4*4];
            uint32_t* d = &Bs[r*136 + c4*4];
            d[0]=tf32r(v.x); d[1]=tf32r(v.y); d[2]=tf32r(v.z); d[3]=tf32r(v.w);
        }
        __syncthreads();
        mma_chunk<8,36,136>(As, Bs, wm, wn, lane, c);
        __syncthreads();
    }
    const int r = lane >> 2, q4 = lane & 3;
    #pragma unroll
    for (int im = 0; im < 2; im++) {
        #pragma unroll
        for (int jn = 0; jn < 8; jn++) {
            const int n = n0 + wn + 8*jn + 2*q4;
            const int hh = n >> 6, nc = n & 63;
            #pragma unroll
            for (int hr = 0; hr < 2; hr++) {
                const int m = m0 + wm + 16*im + r + 8*hr;
                const int b = m >> 11, s = m & 2047;
                *(float2*)&DST[(((size_t)(b*H_ + hh))*S_ + s)*DK_ + nc] =
                    make_float2(c[im][jn][2*hr], c[im][jn][2*hr+1]);
            }
        }
    }
}

// =======================================================================
// K2: k_attn — single-pass attention, FA2-style m-only warp tiling.
// Each of 8 warps owns 16 q-rows x ALL 64 keys of the tile.
// e-stores use __stcs (evict-first): probs are write-once, read-once
// (by k_scale, which bypasses cache) — keeps K/V tiles L2-resident.
// grid (qtile=16, bh=32), 256 threads.
// =======================================================================
__global__ __launch_bounds__(256)
void k_attn(const int* __restrict__ mask, float* __restrict__ attn_ext)
{
    extern __shared__ uint32_t sh[];
    uint32_t* Qs  = sh;                    // [128][68]      8704 w
    uint32_t* Ksb = sh + 8704;             // 2 x [32][72]   4608 w (K^T: [dk][key])
    uint32_t* Vsb = sh + 13312;            // 2 x [32][72]   4608 w ([key][dv])

    float* attn = attn_ext ? attn_ext : g_attn;
    const int bh = blockIdx.y, b = bh >> 4, h = bh & 15;
    const int m0 = blockIdx.x * 128;
    const float* Q = g_q + (size_t)bh * S_ * DK_;
    const float* K = g_k + (size_t)bh * S_ * DK_;
    const float* V = g_v + (size_t)bh * S_ * DK_;
    const int t = threadIdx.x, lane = t & 31, wid = t >> 5;
    const int wm = wid * 16;               // warp owns rows [wm, wm+16)
    const int r8 = lane >> 2, q4 = lane & 3;

    #pragma unroll
    for (int p = 0; p < 8; p++) {          // Q tile 128x64, pitch 68
        int f = t + p*256, rr = f >> 4, c4 = f & 15;
        float4 v = *(const float4*)&Q[(size_t)(m0+rr)*DK_ + c4*4];
        uint32_t* d = &Qs[rr*68 + c4*4];
        d[0]=tf32r(v.x); d[1]=tf32r(v.y); d[2]=tf32r(v.z); d[3]=tf32r(v.w);
    }

    float acc[8][4];
    #pragma unroll
    for (int j=0;j<8;j++)
        #pragma unroll
        for (int k=0;k<4;k++) acc[j][k]=0.f;
    float s0 = 0.f, s1 = 0.f;              // row sums for rows wm+r8, wm+8+r8

    const int qg0 = m0 + wm + r8, qg1 = qg0 + 8;
    const size_t mrow0 = (size_t)b*S_*S_ + (size_t)qg0*S_;
    const size_t mrow1 = (size_t)b*S_*S_ + (size_t)qg1*S_;
    const size_t arow0 = ((size_t)bh*S_ + qg0) * S_;
    const size_t arow1 = ((size_t)bh*S_ + qg1) * S_;

    const int quad_base = lane & ~3;
    const int srcA = quad_base | (q4 >> 1);       // holds dest col q4
    const int srcB = srcA + 2;                    // holds dest col q4+4
    const bool oddq = (q4 & 1);

    for (int kt = 0; kt < 32; kt++) {
        const int n0 = kt * 64;
        __syncthreads();                   // prev iter's mma reads done
        #pragma unroll
        for (int p = 0; p < 4; p++) {      // K 64keys x 64dk -> transposed [dk][key]
            int f = t + p*256, key = f >> 4, c4 = f & 15;
            const int ch = c4 >> 3, colb = (c4 & 7) * 4;
            float4 v = *(const float4*)&K[(size_t)(n0+key)*DK_ + c4*4];
            uint32_t* d = &Ksb[ch*32*72];
            d[(colb+0)*72 + key] = tf32r(v.x);
            d[(colb+1)*72 + key] = tf32r(v.y);
            d[(colb+2)*72 + key] = tf32r(v.z);
            d[(colb+3)*72 + key] = tf32r(v.w);
        }
        #pragma unroll
        for (int p = 0; p < 4; p++) {      // V 64keys x 64 natural [key][dv]
            int f = t + p*256, rr = f >> 4, c4 = f & 15;
            const int ch = rr >> 5;
            float4 v = *(const float4*)&V[(size_t)(n0+rr)*DK_ + c4*4];
            uint32_t* d = &Vsb[ch*32*72 + (rr & 31)*72 + c4*4];
            d[0]=tf32r(v.x); d[1]=tf32r(v.y); d[2]=tf32r(v.z); d[3]=tf32r(v.w);
        }
        __syncthreads();

        // ---- QK^T: c[warp rows 16][64 keys] ----
        float c[8][4];
        #pragma unroll
        for (int j=0;j<8;j++)
            #pragma unroll
            for (int k=0;k<4;k++) c[j][k]=0.f;
        #pragma unroll
        for (int ks = 0; ks < 8; ks++) {   // dk chunks of 8
            const uint32_t* ap = Qs + (size_t)(wm + r8)*68 + 8*ks + q4;
            uint32_t a[4] = { ap[0], ap[8*68], ap[4], ap[8*68 + 4] };
            const uint32_t* Bb = Ksb + (ks >= 4 ? 32*72 : 0) + (size_t)(8*(ks & 3) + q4)*72;
            #pragma unroll
            for (int jn = 0; jn < 8; jn++) {
                uint32_t bfr[2] = { Bb[8*jn + r8], Bb[4*72 + 8*jn + r8] };
                MMA_TF32(c[jn], a, bfr);
            }
        }

        // ---- mask + exp + streaming gmem write + row sums ----
        #pragma unroll
        for (int jn = 0; jn < 8; jn++) {
            const int col = n0 + 8*jn + 2*q4;
            const int2 mk0 = *(const int2*)&mask[mrow0 + col];
            const int2 mk1 = *(const int2*)&mask[mrow1 + col];
            const float p0 = mk0.x ? __expf(c[jn][0] * INVTEMP) : 0.f;
            const float p1 = mk0.y ? __expf(c[jn][1] * INVTEMP) : 0.f;
            const float p2 = mk1.x ? __expf(c[jn][2] * INVTEMP) : 0.f;
            const float p3 = mk1.y ? __expf(c[jn][3] * INVTEMP) : 0.f;
            __stcs((float2*)&attn[arow0 + col], make_float2(p0, p1));
            __stcs((float2*)&attn[arow1 + col], make_float2(p2, p3));
            s0 += p0 + p1;  s1 += p2 + p3;
            c[jn][0] = p0; c[jn][1] = p1; c[jn][2] = p2; c[jn][3] = p3;
        }

        // ---- quad-shuffle C->A fragments, PV mma per 8-key chunk ----
        #pragma unroll
        for (int jb = 0; jb < 8; jb++) {
            const float lo0 = __shfl_sync(0xffffffffu, c[jb][0], srcA);
            const float hi0 = __shfl_sync(0xffffffffu, c[jb][1], srcA);
            const float lo1 = __shfl_sync(0xffffffffu, c[jb][2], srcA);
            const float hi1 = __shfl_sync(0xffffffffu, c[jb][3], srcA);
            const float lo2 = __shfl_sync(0xffffffffu, c[jb][0], srcB);
            const float hi2 = __shfl_sync(0xffffffffu, c[jb][1], srcB);
            const float lo3 = __shfl_sync(0xffffffffu, c[jb][2], srcB);
            const float hi3 = __shfl_sync(0xffffffffu, c[jb][3], srcB);
            uint32_t a[4];
            a[0] = tf32r(oddq ? hi0 : lo0);
            a[1] = tf32r(oddq ? hi1 : lo1);
            a[2] = tf32r(oddq ? hi2 : lo2);
            a[3] = tf32r(oddq ? hi3 : lo3);
            const uint32_t* Vb = Vsb + (jb >= 4 ? 32*72 : 0) + (size_t)(8*(jb & 3) + q4)*72;
            #pragma unroll
            for (int jn = 0; jn < 8; jn++) {
                uint32_t bfr[2] = { Vb[8*jn + r8], Vb[4*72 + 8*jn + r8] };
                MMA_TF32(acc[jn], a, bfr);
            }
        }
    }

    // ---- row sums complete within quad ----
    s0 += __shfl_xor_sync(0xffffffffu, s0, 1);
    s0 += __shfl_xor_sync(0xffffffffu, s0, 2);
    s1 += __shfl_xor_sync(0xffffffffu, s1, 1);
    s1 += __shfl_xor_sync(0xffffffffu, s1, 2);
    if (q4 == 0) {
        g_rsum[bh*S_ + qg0] = s0;
        g_rsum[bh*S_ + qg1] = s1;
    }
    const float inv0 = 1.f / s0, inv1 = 1.f / s1;

    // ---- epilogue: O merged [b*S+q][h*64+n] ----
    float* orow0 = &g_o[(size_t)(b*S_ + qg0)*D_ + h*DK_];
    float* orow1 = &g_o[(size_t)(b*S_ + qg1)*D_ + h*DK_];
    #pragma unroll
    for (int jn = 0; jn < 8; jn++) {
        const int n = 8*jn + 2*q4;
        *(float2*)&orow0[n] = make_float2(acc[jn][0] * inv0, acc[jn][1] * inv0);
        *(float2*)&orow1[n] = make_float2(acc[jn][2] * inv1, acc[jn][3] * inv1);
    }
}

// =======================================================================
// K3: k_scale — attn *= 1/rowsum.  4 rows/CTA, 8 batched float4 ldcs
// (MLP=8) then 8 stcs; full cache bypass. grid = BH_*S_/4 = 16384.
// =======================================================================
__global__ __launch_bounds__(256)
void k_scale(float* __restrict__ attn_ext)
{
    float* attn = attn_ext ? attn_ext : g_attn;
    const int row0 = blockIdx.x * 4;
    const int t = threadIdx.x;

    float inv[4];
    #pragma unroll
    for (int r = 0; r < 4; r++) inv[r] = 1.f / g_rsum[row0 + r];

    // each row: 512 float4; 256 threads -> 2 f4/row/thread; 4 rows -> 8 f4
    float4 v[8];
    #pragma unroll
    for (int r = 0; r < 4; r++) {
        float4* p = (float4*)(attn + (size_t)(row0 + r) * S_);
        v[2*r]   = __ldcs(p + t);
        v[2*r+1] = __ldcs(p + t + 256);
    }
    #pragma unroll
    for (int r = 0; r < 4; r++) {
        const float s = inv[r];
        v[2*r].x   *= s; v[2*r].y   *= s; v[2*r].z   *= s; v[2*r].w   *= s;
        v[2*r+1].x *= s; v[2*r+1].y *= s; v[2*r+1].z *= s; v[2*r+1].w *= s;
    }
    #pragma unroll
    for (int r = 0; r < 4; r++) {
        float4* p = (float4*)(attn + (size_t)(row0 + r) * S_);
        __stcs(p + t,       v[2*r]);
        __stcs(p + t + 256, v[2*r+1]);
    }
}

// =======================================================================
// K4: fc = O[4096,1024] @ w_fc[1024,1024] + residual (tf32)
// =======================================================================
__global__ __launch_bounds__(256)
void k_fc(const float* __restrict__ X, const float* __restrict__ W)
{
    __shared__ uint32_t As[128*36];
    __shared__ uint32_t Bs[32*136];
    const int n0 = blockIdx.x * 128, m0 = blockIdx.y * 128;
    const int t = threadIdx.x, lane = t & 31, wid = t >> 5;
    const int wm = (wid & 3) * 32, wn = (wid >> 2) * 64;

    float c[2][8][4];
    #pragma unroll
    for (int i=0;i<2;i++)
        #pragma unroll
        for (int j=0;j<8;j++)
            #pragma unroll
            for (int k=0;k<4;k++) c[i][j][k]=0.f;

    for (int k0 = 0; k0 < 1024; k0 += 32) {
        #pragma unroll
        for (int p = 0; p < 4; p++) {
            int f = t + p*256, r = f >> 3, c4 = f & 7;
            float4 v = *(const float4*)&g_o[(size_t)(m0+r)*1024 + k0 + c4*4];
            uint32_t* d = &As[r*36 + c4*4];
            d[0]=tf32r(v.x); d[1]=tf32r(v.y); d[2]=tf32r(v.z); d[3]=tf32r(v.w);
        }
        #pragma unroll
        for (int p = 0; p < 4; p++) {
            int f = t + p*256, r = f >> 5, c4 = f & 31;
            float4 v = *(const float4*)&W[(size_t)(k0+r)*1024 + n0 + c4*4];
            uint32_t* d = &Bs[r*136 + c4*4];
            d[0]=tf32r(v.x); d[1]=tf32r(v.y); d[2]=tf32r(v.z); d[3]=tf32r(v.w);
        }
        __syncthreads();
        mma_chunk<8,36,136>(As, Bs, wm, wn, lane, c);
        __syncthreads();
    }
    const int r = lane >> 2, q4 = lane & 3;
    #pragma unroll
    for (int im = 0; im < 2; im++) {
        #pragma unroll
        for (int hr = 0; hr < 2; hr++) {
            const int m = m0 + wm + 16*im + r + 8*hr;
            #pragma unroll
            for (int jn = 0; jn < 8; jn++) {
                const int n = n0 + wn + 8*jn + 2*q4;
                const float2 res = *(const float2*)&X[(size_t)m*D_ + n];
                *(float2*)&g_fc[(size_t)m*D_ + n] =
                    make_float2(c[im][jn][2*hr] + res.x, c[im][jn][2*hr+1] + res.y);
            }
        }
    }
}

// =======================================================================
// K5: LayerNorm over last dim (1024), write final out region.
// =======================================================================
__global__ __launch_bounds__(256)
void k_ln(const float* __restrict__ gamma, const float* __restrict__ beta,
          float* __restrict__ out)
{
    __shared__ float red[8];
    const int m = blockIdx.x, t = threadIdx.x;
    const float* x = g_fc + (size_t)m * D_;
    float v[4];
    #pragma unroll
    for (int u = 0; u < 4; u++) v[u] = x[t + 256 * u];
    float s = v[0] + v[1] + v[2] + v[3];
    const float mu = bred_sum(s, red) * (1.0f / D_);
    float d2 = 0.f;
    #pragma unroll
    for (int u = 0; u < 4; u++) { float d = v[u] - mu; d2 += d * d; }
    const float var = bred_sum(d2, red) * (1.0f / D_);
    const float rstd = rsqrtf(var + LNEPS);
    #pragma unroll
    for (int u = 0; u < 4; u++) {
        const int c = t + 256 * u;
        out[(size_t)m * D_ + c] = (v[u] - mu) * rstd * gamma[c] + beta[c];
    }
}

// =======================================================================
extern "C" void kernel_launch(void* const* d_in, const int* in_sizes, int n_in,
                              void* d_out, int out_size)
{
    (void)in_sizes; (void)n_in;
    const float* qkv  = (const float*)d_in[0];
    const int*   mask = (const int*)  d_in[1];
    const float* w_qs = (const float*)d_in[2];
    const float* w_ks = (const float*)d_in[3];
    const float* w_vs = (const float*)d_in[4];
    const float* w_fc = (const float*)d_in[5];
    const float* ga   = (const float*)d_in[6];
    const float* be   = (const float*)d_in[7];
    float* out = (float*)d_out;

    const int OUT_ELEMS  = M_ * D_;                        // 4194304
    const long long ATTN_ELEMS = (long long)BH_ * S_ * S_; // 134217728
    float* attn_ext = ((long long)out_size >= OUT_ELEMS + ATTN_ELEMS)
                        ? out + OUT_ELEMS : nullptr;

    const int SMEM_ATTN = (8704 + 4608 + 4608) * 4;        // 71680 B
    cudaFuncSetAttribute(k_attn, cudaFuncAttributeMaxDynamicSharedMemorySize, SMEM_ATTN);

    k_proj  <<<dim3(8, 32, 3), 256>>>(qkv, w_qs, w_ks, w_vs);
    k_attn  <<<dim3(16, 32), 256, SMEM_ATTN>>>(mask, attn_ext);
    k_scale <<<BH_ * S_ / 4, 256>>>(attn_ext);
    k_fc    <<<dim3(8, 32), 256>>>(qkv, w_fc);
    k_ln    <<<M_, 256>>>(ga, be, out);
}